// round 13
// baseline (speedup 1.0000x reference)
#include <cuda_runtime.h>
#include <math.h>

#define NPROP 8192
#define NC 81
#define NFG 80
#define NDET 100
#define SCORE_T 0.05f
#define NMS_T 0.5f
#define BBOX_CLIP 4.135166556742356f   // log(1000/16)
#define CAP 384                         // max survivors/class (E[M]~235, ~10 sigma)
#define NW64 6                          // 64-bit mask words per row
#define NW32 12                         // 32-bit words per row
#define T2 256
#define CLU 2                           // cluster size: 160 CTAs <= 148+spill -> ~1 wave
#define FULLM 0xffffffffu

// Scratch (no cudaMalloc)
__device__ int   g_count[NFG];          // zero at load; nms resets per replay
__device__ int   g_cn[NFG * NPROP];
__device__ float g_cs[NFG * NPROP];

// ---------------------------------------------------------------------------
// Kernel 1: softmax + score-threshold push. 8 lanes per proposal,
// 32 proposals per block, logits staged through smem via LDG.128.
// ---------------------------------------------------------------------------
#define SM_PROPS 32
__global__ void __launch_bounds__(256, 1)
softmax_kernel(const float* __restrict__ logits) {
    __shared__ float slog[SM_PROPS * NC];          // 10368 B
    const int tid = threadIdx.x;

    const float4* src = (const float4*)(logits + (size_t)blockIdx.x * SM_PROPS * NC);
    float4* dst = (float4*)slog;
    #pragma unroll
    for (int k = 0; k < 3; k++) {
        int idx = tid + k * 256;
        if (idx < (SM_PROPS * NC) / 4) dst[idx] = src[idx];
    }
    __syncthreads();

    const int p  = tid >> 3;
    const int l8 = tid & 7;
    const int n  = blockIdx.x * SM_PROPS + p;
    const float* row = slog + p * NC;

    float v[11];
    #pragma unroll
    for (int k = 0; k < 10; k++) v[k] = row[l8 + 8 * k];
    v[10] = (l8 == 0) ? row[80] : -INFINITY;

    float mx = v[0];
    #pragma unroll
    for (int k = 1; k < 11; k++) mx = fmaxf(mx, v[k]);
    mx = fmaxf(mx, __shfl_xor_sync(FULLM, mx, 1));
    mx = fmaxf(mx, __shfl_xor_sync(FULLM, mx, 2));
    mx = fmaxf(mx, __shfl_xor_sync(FULLM, mx, 4));

    float e[11];
    float sum = 0.0f;
    #pragma unroll
    for (int k = 0; k < 11; k++) { e[k] = expf(v[k] - mx); sum += e[k]; }
    sum += __shfl_xor_sync(FULLM, sum, 1);
    sum += __shfl_xor_sync(FULLM, sum, 2);
    sum += __shfl_xor_sync(FULLM, sum, 4);

    #pragma unroll
    for (int k = 0; k < 11; k++) {
        int cls = l8 + 8 * k;
        if (cls >= 1 && cls < NC) {
            float sc = e[k] / sum;
            if (sc >= SCORE_T) {
                int cc = cls - 1;
                int pos = atomicAdd(&g_count[cc], 1);
                g_cn[cc * NPROP + pos] = n;
                g_cs[cc * NPROP + pos] = sc;
            }
        }
    }
}

// ---------------------------------------------------------------------------
// Box decode (Fast R-CNN BoxCoder + clip to image)
// ---------------------------------------------------------------------------
__device__ __forceinline__ float4 decode_box(float4 p, float4 d, float W, float H) {
    float w  = p.z - p.x;
    float h  = p.w - p.y;
    float cx = p.x + 0.5f * w;
    float cy = p.y + 0.5f * h;
    float dx = d.x / 10.0f;
    float dy = d.y / 10.0f;
    float dw = fminf(d.z / 5.0f, BBOX_CLIP);
    float dh = fminf(d.w / 5.0f, BBOX_CLIP);
    float pcx = dx * w + cx;
    float pcy = dy * h + cy;
    float pw  = expf(dw) * w;
    float ph  = expf(dh) * h;
    float x1 = fminf(fmaxf(pcx - 0.5f * pw, 0.0f), W);
    float y1 = fminf(fmaxf(pcy - 0.5f * ph, 0.0f), H);
    float x2 = fminf(fmaxf(pcx + 0.5f * pw, 0.0f), W);
    float y2 = fminf(fmaxf(pcy + 0.5f * ph, 0.0f), H);
    return make_float4(x1, y1, x2, y2);
}

// OR a bit into cluster-rank-0's shared mask (callable from any rank)
__device__ __forceinline__ void cluster_or32(unsigned* p, unsigned val) {
    unsigned laddr = (unsigned)__cvta_generic_to_shared(p);
    unsigned raddr;
    asm volatile("mapa.shared::cluster.u32 %0, %1, 0;" : "=r"(raddr) : "r"(laddr));
    asm volatile("red.relaxed.cluster.shared::cluster.or.b32 [%0], %1;"
                 :: "r"(raddr), "r"(val) : "memory");
}

// Plain store into cluster-rank-0's shared memory
__device__ __forceinline__ void cluster_st32(int* p, int val) {
    unsigned laddr = (unsigned)__cvta_generic_to_shared(p);
    unsigned raddr;
    asm volatile("mapa.shared::cluster.u32 %0, %1, 0;" : "=r"(raddr) : "r"(laddr));
    asm volatile("st.shared::cluster.u32 [%0], %1;"
                 :: "r"(raddr), "r"(val) : "memory");
}

// ---------------------------------------------------------------------------
// Kernel 2 (PDL secondary, 2-CTA cluster per class):
//  pre-sync: zero smem mask (overlaps softmax via programmatic launch)
//  post-sync: decode (early loads) -> cluster-split rank scatter ->
//  cluster-split triangular pair mask (DSMEM red.or) -> warp greedy scan
//  (register rows, 2-way speculative accepts) -> output.
// Output (float32): boxes[8000*4] | scores[8000] | labels[8000] | valid[8000]
// ---------------------------------------------------------------------------
__global__ void __launch_bounds__(T2, 1) __cluster_dims__(CLU, 1, 1)
nms_fused(const float* __restrict__ proposal,
          const float* __restrict__ regs,
          const int* __restrict__ imh,
          const int* __restrict__ imw,
          float* __restrict__ out) {
    __shared__ float4 sbox[CAP];
    __shared__ unsigned long long skey[CAP];
    __shared__ unsigned long long smask64[CAP * NW64];   // 18 KB
    __shared__ int sidx[CAP];
    __shared__ int aidx[NDET];
    __shared__ unsigned ascr[NDET];
    __shared__ int shNa;
    __shared__ float4 shB0;
    unsigned* smask32 = (unsigned*)smask64;

    const int c   = blockIdx.x / CLU;
    const int tid = threadIdx.x;
    unsigned crank;
    asm("mov.u32 %0, %%cluster_ctarank;" : "=r"(crank));

    // -------- pre-dependency work: zero the suppression mask --------
    for (int i = tid; i < CAP * NW64; i += T2) smask64[i] = 0ull;

    // wait for softmax kernel results (no-op if launched without PDL)
    cudaGridDependencySynchronize();

    int M = g_count[c];
    if (M > CAP) M = CAP;

    float W = 1216.0f, H = 800.0f;
    if (imw) {
        int vw = *imw, vh = *imh;
        W = (vw > 0 && vw < 100000) ? (float)vw : __int_as_float(vw);
        H = (vh > 0 && vh < 100000) ? (float)vh : __int_as_float(vh);
    }

    const float4* prop4 = (const float4*)proposal;
    const float4* reg4  = (const float4*)regs;       // row n = 81 float4 deltas

    // ---- decode survivors; first T2 indices with early-issued loads ----
    int n0 = -1; float sc0 = 0.0f; float4 pb0, db0;
    if (tid < M) {
        n0  = g_cn[c * NPROP + tid];
        sc0 = g_cs[c * NPROP + tid];
        pb0 = prop4[n0];
        db0 = reg4[(size_t)n0 * NC + (c + 1)];
    }
    if (tid < M) {
        float4 b = decode_box(pb0, db0, W, H);
        bool keep = ((b.z - b.x) >= 1.0f) && ((b.w - b.y) >= 1.0f);
        sbox[tid] = b;
        unsigned hi = keep ? __float_as_uint(sc0) : 0u;
        skey[tid] = ((unsigned long long)hi << 32)
                  | (unsigned long long)(0xFFFFFFFFu - (unsigned)n0);
    }
    for (int i = tid + T2; i < M; i += T2) {         // rare: M > 256
        int   n = g_cn[c * NPROP + i];
        float s = g_cs[c * NPROP + i];
        float4 b = decode_box(prop4[n], reg4[(size_t)n * NC + (c + 1)], W, H);
        bool keep = ((b.z - b.x) >= 1.0f) && ((b.w - b.y) >= 1.0f);
        sbox[i] = b;
        unsigned hi = keep ? __float_as_uint(s) : 0u;
        skey[i] = ((unsigned long long)hi << 32)
                | (unsigned long long)(0xFFFFFFFFu - (unsigned)n);
    }
    if (crank == 0 && tid == 0) shB0 = decode_box(prop4[0], reg4[c + 1], W, H);
    __syncthreads();

    // cluster sync #1: masks zeroed + decode done everywhere
    asm volatile("barrier.cluster.arrive.aligned;" ::: "memory");
    asm volatile("barrier.cluster.wait.aligned;"   ::: "memory");
    if (crank == 0 && tid == 0) g_count[c] = 0;      // reset for next replay

    // ---- rank scatter, split across cluster: CTA r ranks its M/CLU slice ----
    {
        int s0 = ((int)crank * M) / CLU;
        int s1 = (((int)crank + 1) * M) / CLU;
        int i  = s0 + tid;
        if (i < s1) {
            unsigned long long ki = skey[i];
            int rk = 0;
            for (int j = 0; j < M; j++) rk += (skey[j] > ki) ? 1 : 0;
            cluster_st32(&sidx[rk], i);              // keys unique -> permutation
        }
    }

    // ---- triangular pair mask, split across cluster (CLU*T2 lanes) ----
    {
        long long npairs = (long long)M * (M - 1) / 2;
        const int TT = CLU * T2;                     // 512 lanes per class
        int gt = (int)crank * T2 + tid;
        long long p0 = npairs * gt / TT;
        long long p1 = npairs * (gt + 1) / TT;
        if (p0 < p1) {
            int j = (int)((1.0f + sqrtf((float)(8.0 * (double)p0 + 1.0))) * 0.5f);
            while ((long long)j * (j - 1) / 2 > p0) j--;
            while ((long long)(j + 1) * j / 2 <= p0) j++;
            int i = (int)(p0 - (long long)j * (j - 1) / 2);

            unsigned long long kj = skey[j];
            float4 bj = sbox[j];
            float  aj = (bj.z - bj.x) * (bj.w - bj.y);
            for (long long p = p0; p < p1; p++) {
                unsigned long long ki = skey[i];
                float4 bi = sbox[i];
                float  ai = (bi.z - bi.x) * (bi.w - bi.y);
                float lx = fmaxf(bi.x, bj.x);
                float ly = fmaxf(bi.y, bj.y);
                float rx = fminf(bi.z, bj.z);
                float ry = fminf(bi.w, bj.w);
                float iw = fmaxf(rx - lx, 0.0f);
                float ih = fmaxf(ry - ly, 0.0f);
                float inter = iw * ih;
                float iou = inter / (ai + aj - inter + 1e-12f);
                if (iou > NMS_T) {
                    int loser  = (kj > ki) ? i : j;
                    int winner = (kj > ki) ? j : i;
                    cluster_or32(&smask32[loser * NW32 + (winner >> 5)],
                                 1u << (winner & 31));
                }
                if (++i == j) {
                    i = 0; j++;
                    kj = skey[j]; bj = sbox[j];
                    aj = (bj.z - bj.x) * (bj.w - bj.y);
                }
            }
        }
    }

    // cluster sync #2: all sidx stores + mask bits landed in rank 0
    asm volatile("barrier.cluster.arrive.aligned;" ::: "memory");
    asm volatile("barrier.cluster.wait.aligned;"   ::: "memory");
    if (crank != 0) return;

    // ---- warp greedy scan: register rows + 2-way speculative accepts ----
    if (tid < 32) {
        const int lane = tid;
        unsigned long long a0 = 0, a1 = 0, a2 = 0, a3 = 0, a4 = 0, a5 = 0;
        int na = 0;
        for (int chunk = 0; chunk * 32 < M && na < NDET; chunk++) {
            int r = chunk * 32 + lane;
            bool haveR = (r < M);
            int i = haveR ? sidx[r] : 0;
            unsigned sc = haveR ? (unsigned)(skey[i] >> 32) : 0u;
            bool alive = (sc != 0u);
            unsigned long long r0 = 0, r1 = 0, r2 = 0, r3 = 0, r4 = 0, r5 = 0;
            if (haveR) {
                const unsigned long long* row = &smask64[i * NW64];
                r0 = row[0]; r1 = row[1]; r2 = row[2];
                r3 = row[3]; r4 = row[4]; r5 = row[5];
            }
            unsigned long long sup = (r0 & a0) | (r1 & a1) | (r2 & a2)
                                   | (r3 & a3) | (r4 & a4) | (r5 & a5);
            unsigned pend   = __ballot_sync(FULLM, alive && (sup == 0ull));
            unsigned aliveb = __ballot_sync(FULLM, alive);
            while (pend && na < NDET) {
                int l1 = __ffs(pend) - 1;
                unsigned rem = pend & (pend - 1);
                int l2 = rem ? (__ffs(rem) - 1) : -1;
                int i1 = __shfl_sync(FULLM, i, l1);
                int i2 = __shfl_sync(FULLM, i, (l2 >= 0) ? l2 : l1);
                // own-row suppression bits for i1 / i2 (register selects)
                int w1 = i1 >> 6;
                unsigned long long sel1 = (w1 == 0) ? r0 : (w1 == 1) ? r1
                                        : (w1 == 2) ? r2 : (w1 == 3) ? r3
                                        : (w1 == 4) ? r4 : r5;
                bool b1 = (sel1 >> (i1 & 63)) & 1ull;
                int w2 = i2 >> 6;
                unsigned long long sel2 = (w2 == 0) ? r0 : (w2 == 1) ? r1
                                        : (w2 == 2) ? r2 : (w2 == 3) ? r3
                                        : (w2 == 4) ? r4 : r5;
                bool b2 = (sel2 >> (i2 & 63)) & 1ull;
                unsigned s1 = __ballot_sync(FULLM, b1);
                unsigned s2 = __ballot_sync(FULLM, b2);
                // accept l1
                if (lane == l1) { aidx[na] = i; ascr[na] = sc; }
                na++;
                {
                    unsigned long long b = 1ull << (i1 & 63);
                    a0 |= (w1 == 0) ? b : 0ull; a1 |= (w1 == 1) ? b : 0ull;
                    a2 |= (w1 == 2) ? b : 0ull; a3 |= (w1 == 3) ? b : 0ull;
                    a4 |= (w1 == 4) ? b : 0ull; a5 |= (w1 == 5) ? b : 0ull;
                }
                pend = rem & ~s1;       // drop lanes suppressed by i1 (incl l2 if hit)
                bool ok2 = (l2 >= 0) && (na < NDET) && !((s1 >> l2) & 1u);
                if (ok2) {
                    if (lane == l2) { aidx[na] = i; ascr[na] = sc; }
                    na++;
                    unsigned long long b = 1ull << (i2 & 63);
                    a0 |= (w2 == 0) ? b : 0ull; a1 |= (w2 == 1) ? b : 0ull;
                    a2 |= (w2 == 2) ? b : 0ull; a3 |= (w2 == 3) ? b : 0ull;
                    a4 |= (w2 == 4) ? b : 0ull; a5 |= (w2 == 5) ? b : 0ull;
                    pend &= ~(1u << l2);
                    pend &= ~s2;        // drop lanes suppressed by i2
                }
            }
            if (na == NDET || aliveb != FULLM) break;  // done / later ranks dead
        }
        if (lane == 0) shNa = na;
    }
    __syncthreads();

    // ---- parallel output ----
    const int obase = c * NDET * 4;
    const int sbase = NFG * NDET * 4;        // 32000
    const int lbase = sbase + NFG * NDET;    // 40000
    const int vbase = lbase + NFG * NDET;    // 48000
    const float label = (float)(c + 1);
    const int na = shNa;

    for (int a = tid; a < na; a += T2) {
        float4 b = sbox[aidx[a]];
        out[obase + a * 4 + 0] = b.x;
        out[obase + a * 4 + 1] = b.y;
        out[obase + a * 4 + 2] = b.z;
        out[obase + a * 4 + 3] = b.w;
        int slot = c * NDET + a;
        out[sbase + slot] = __uint_as_float(ascr[a]);
        out[lbase + slot] = label;
        out[vbase + slot] = 1.0f;
    }
    const float4 b0 = shB0;
    for (int jt = na + tid; jt < NDET; jt += T2) {
        out[obase + jt * 4 + 0] = b0.x;
        out[obase + jt * 4 + 1] = b0.y;
        out[obase + jt * 4 + 2] = b0.z;
        out[obase + jt * 4 + 3] = b0.w;
        int slot = c * NDET + jt;
        out[sbase + slot] = 0.0f;
        out[lbase + slot] = label;
        out[vbase + slot] = 0.0f;
    }
}

extern "C" void kernel_launch(void* const* d_in, const int* in_sizes, int n_in,
                              void* d_out, int out_size) {
    const float* proposal = (const float*)d_in[0];
    const float* logits   = (const float*)d_in[1];
    const float* regs     = (const float*)d_in[2];
    const int*   imh      = (n_in >= 5) ? (const int*)d_in[3] : nullptr;
    const int*   imw      = (n_in >= 5) ? (const int*)d_in[4] : nullptr;
    float* outf = (float*)d_out;

    softmax_kernel<<<NPROP / SM_PROPS, 256>>>(logits);

    // PDL launch: nms ramps up while softmax still runs.
    cudaLaunchConfig_t cfg = {};
    cfg.gridDim  = dim3(NFG * CLU, 1, 1);
    cfg.blockDim = dim3(T2, 1, 1);
    cudaLaunchAttribute attrs[1];
    attrs[0].id = cudaLaunchAttributeProgrammaticStreamSerialization;
    attrs[0].val.programmaticStreamSerializationAllowed = 1;
    cfg.attrs = attrs;
    cfg.numAttrs = 1;
    cudaError_t err = cudaLaunchKernelEx(&cfg, nms_fused,
                                         proposal, regs, imh, imw, outf);
    if (err != cudaSuccess) {
        nms_fused<<<NFG * CLU, T2>>>(proposal, regs, imh, imw, outf);
    }
}

// round 14
// speedup vs baseline: 1.1782x; 1.1782x over previous
#include <cuda_runtime.h>
#include <math.h>

#define NPROP 8192
#define NC 81
#define NFG 80
#define NDET 100
#define SCORE_T 0.05f
#define NMS_T 0.5f
#define BBOX_CLIP 4.135166556742356f   // log(1000/16)
#define CAP 384                         // max survivors/class (E[M]~235, ~10 sigma)
#define NW64 6                          // 64-bit mask words per row
#define NW32 12                         // 32-bit words per row
#define T2 256
#define CLU 4                           // cluster size (CTAs per class) — R12 best
#define FULLM 0xffffffffu

// Scratch (no cudaMalloc)
__device__ int   g_count[NFG];          // zero at load; nms resets per replay
__device__ int   g_cn[NFG * NPROP];
__device__ float g_cs[NFG * NPROP];

// ---------------------------------------------------------------------------
// Kernel 1: softmax + score-threshold push. 8 lanes per proposal,
// 32 proposals per block, logits staged through smem via LDG.128.
// ---------------------------------------------------------------------------
#define SM_PROPS 32
__global__ void __launch_bounds__(256, 1)
softmax_kernel(const float* __restrict__ logits) {
    __shared__ float slog[SM_PROPS * NC];          // 10368 B
    const int tid = threadIdx.x;

    const float4* src = (const float4*)(logits + (size_t)blockIdx.x * SM_PROPS * NC);
    float4* dst = (float4*)slog;
    #pragma unroll
    for (int k = 0; k < 3; k++) {
        int idx = tid + k * 256;
        if (idx < (SM_PROPS * NC) / 4) dst[idx] = src[idx];
    }
    __syncthreads();

    const int p  = tid >> 3;
    const int l8 = tid & 7;
    const int n  = blockIdx.x * SM_PROPS + p;
    const float* row = slog + p * NC;

    float v[11];
    #pragma unroll
    for (int k = 0; k < 10; k++) v[k] = row[l8 + 8 * k];
    v[10] = (l8 == 0) ? row[80] : -INFINITY;

    float mx = v[0];
    #pragma unroll
    for (int k = 1; k < 11; k++) mx = fmaxf(mx, v[k]);
    mx = fmaxf(mx, __shfl_xor_sync(FULLM, mx, 1));
    mx = fmaxf(mx, __shfl_xor_sync(FULLM, mx, 2));
    mx = fmaxf(mx, __shfl_xor_sync(FULLM, mx, 4));

    float e[11];
    float sum = 0.0f;
    #pragma unroll
    for (int k = 0; k < 11; k++) { e[k] = expf(v[k] - mx); sum += e[k]; }
    sum += __shfl_xor_sync(FULLM, sum, 1);
    sum += __shfl_xor_sync(FULLM, sum, 2);
    sum += __shfl_xor_sync(FULLM, sum, 4);

    #pragma unroll
    for (int k = 0; k < 11; k++) {
        int cls = l8 + 8 * k;
        if (cls >= 1 && cls < NC) {
            float sc = e[k] / sum;
            if (sc >= SCORE_T) {
                int cc = cls - 1;
                int pos = atomicAdd(&g_count[cc], 1);
                g_cn[cc * NPROP + pos] = n;
                g_cs[cc * NPROP + pos] = sc;
            }
        }
    }
}

// ---------------------------------------------------------------------------
// Box decode (Fast R-CNN BoxCoder + clip to image)
// ---------------------------------------------------------------------------
__device__ __forceinline__ float4 decode_box(float4 p, float4 d, float W, float H) {
    float w  = p.z - p.x;
    float h  = p.w - p.y;
    float cx = p.x + 0.5f * w;
    float cy = p.y + 0.5f * h;
    float dx = d.x / 10.0f;
    float dy = d.y / 10.0f;
    float dw = fminf(d.z / 5.0f, BBOX_CLIP);
    float dh = fminf(d.w / 5.0f, BBOX_CLIP);
    float pcx = dx * w + cx;
    float pcy = dy * h + cy;
    float pw  = expf(dw) * w;
    float ph  = expf(dh) * h;
    float x1 = fminf(fmaxf(pcx - 0.5f * pw, 0.0f), W);
    float y1 = fminf(fmaxf(pcy - 0.5f * ph, 0.0f), H);
    float x2 = fminf(fmaxf(pcx + 0.5f * pw, 0.0f), W);
    float y2 = fminf(fmaxf(pcy + 0.5f * ph, 0.0f), H);
    return make_float4(x1, y1, x2, y2);
}

// OR a bit into cluster-rank-0's shared mask (callable from any rank)
__device__ __forceinline__ void cluster_or32(unsigned* p, unsigned val) {
    unsigned laddr = (unsigned)__cvta_generic_to_shared(p);
    unsigned raddr;
    asm volatile("mapa.shared::cluster.u32 %0, %1, 0;" : "=r"(raddr) : "r"(laddr));
    asm volatile("red.relaxed.cluster.shared::cluster.or.b32 [%0], %1;"
                 :: "r"(raddr), "r"(val) : "memory");
}

// Plain store into cluster-rank-0's shared memory
__device__ __forceinline__ void cluster_st32(int* p, int val) {
    unsigned laddr = (unsigned)__cvta_generic_to_shared(p);
    unsigned raddr;
    asm volatile("mapa.shared::cluster.u32 %0, %1, 0;" : "=r"(raddr) : "r"(laddr));
    asm volatile("st.shared::cluster.u32 [%0], %1;"
                 :: "r"(raddr), "r"(val) : "memory");
}

// ---------------------------------------------------------------------------
// Kernel 2 (PDL secondary, 4-CTA cluster per class):
//  pre-sync: zero smem mask (overlaps softmax via programmatic launch)
//  post-sync: decode (early loads) -> cluster-split rank scatter ->
//  cluster-split triangular pair mask (DSMEM red.or) -> warp greedy scan
//  (register rows, 2-way speculative accepts) -> output.
// Output (float32): boxes[8000*4] | scores[8000] | labels[8000] | valid[8000]
// ---------------------------------------------------------------------------
__global__ void __launch_bounds__(T2, 1) __cluster_dims__(CLU, 1, 1)
nms_fused(const float* __restrict__ proposal,
          const float* __restrict__ regs,
          const int* __restrict__ imh,
          const int* __restrict__ imw,
          float* __restrict__ out) {
    __shared__ float4 sbox[CAP];
    __shared__ unsigned long long skey[CAP];
    __shared__ unsigned long long smask64[CAP * NW64];   // 18 KB
    __shared__ int sidx[CAP];
    __shared__ int aidx[NDET];
    __shared__ unsigned ascr[NDET];
    __shared__ int shNa;
    __shared__ float4 shB0;
    unsigned* smask32 = (unsigned*)smask64;

    const int c   = blockIdx.x / CLU;
    const int tid = threadIdx.x;
    unsigned crank;
    asm("mov.u32 %0, %%cluster_ctarank;" : "=r"(crank));

    // -------- pre-dependency work: zero the suppression mask --------
    for (int i = tid; i < CAP * NW64; i += T2) smask64[i] = 0ull;

    // wait for softmax kernel results (no-op if launched without PDL)
    cudaGridDependencySynchronize();

    int M = g_count[c];
    if (M > CAP) M = CAP;

    float W = 1216.0f, H = 800.0f;
    if (imw) {
        int vw = *imw, vh = *imh;
        W = (vw > 0 && vw < 100000) ? (float)vw : __int_as_float(vw);
        H = (vh > 0 && vh < 100000) ? (float)vh : __int_as_float(vh);
    }

    const float4* prop4 = (const float4*)proposal;
    const float4* reg4  = (const float4*)regs;       // row n = 81 float4 deltas

    // ---- decode survivors; first T2 indices with early-issued loads ----
    int n0 = -1; float sc0 = 0.0f; float4 pb0, db0;
    if (tid < M) {
        n0  = g_cn[c * NPROP + tid];
        sc0 = g_cs[c * NPROP + tid];
        pb0 = prop4[n0];
        db0 = reg4[(size_t)n0 * NC + (c + 1)];
    }
    if (tid < M) {
        float4 b = decode_box(pb0, db0, W, H);
        bool keep = ((b.z - b.x) >= 1.0f) && ((b.w - b.y) >= 1.0f);
        sbox[tid] = b;
        unsigned hi = keep ? __float_as_uint(sc0) : 0u;
        skey[tid] = ((unsigned long long)hi << 32)
                  | (unsigned long long)(0xFFFFFFFFu - (unsigned)n0);
    }
    for (int i = tid + T2; i < M; i += T2) {         // rare: M > 256
        int   n = g_cn[c * NPROP + i];
        float s = g_cs[c * NPROP + i];
        float4 b = decode_box(prop4[n], reg4[(size_t)n * NC + (c + 1)], W, H);
        bool keep = ((b.z - b.x) >= 1.0f) && ((b.w - b.y) >= 1.0f);
        sbox[i] = b;
        unsigned hi = keep ? __float_as_uint(s) : 0u;
        skey[i] = ((unsigned long long)hi << 32)
                | (unsigned long long)(0xFFFFFFFFu - (unsigned)n);
    }
    if (crank == 0 && tid == 0) shB0 = decode_box(prop4[0], reg4[c + 1], W, H);
    __syncthreads();

    // cluster sync #1: masks zeroed + decode done everywhere
    asm volatile("barrier.cluster.arrive.aligned;" ::: "memory");
    asm volatile("barrier.cluster.wait.aligned;"   ::: "memory");
    if (crank == 0 && tid == 0) g_count[c] = 0;      // reset for next replay

    // ---- rank scatter, split across cluster: CTA r ranks its M/CLU slice ----
    {
        int s0 = ((int)crank * M) / CLU;
        int s1 = (((int)crank + 1) * M) / CLU;
        int i  = s0 + tid;
        if (i < s1) {
            unsigned long long ki = skey[i];
            int rk = 0;
            for (int j = 0; j < M; j++) rk += (skey[j] > ki) ? 1 : 0;
            cluster_st32(&sidx[rk], i);              // keys unique -> permutation
        }
    }

    // ---- triangular pair mask, split across cluster (CLU*T2 lanes) ----
    {
        long long npairs = (long long)M * (M - 1) / 2;
        const int TT = CLU * T2;                     // 1024 lanes per class
        int gt = (int)crank * T2 + tid;
        long long p0 = npairs * gt / TT;
        long long p1 = npairs * (gt + 1) / TT;
        if (p0 < p1) {
            int j = (int)((1.0f + sqrtf((float)(8.0 * (double)p0 + 1.0))) * 0.5f);
            while ((long long)j * (j - 1) / 2 > p0) j--;
            while ((long long)(j + 1) * j / 2 <= p0) j++;
            int i = (int)(p0 - (long long)j * (j - 1) / 2);

            unsigned long long kj = skey[j];
            float4 bj = sbox[j];
            float  aj = (bj.z - bj.x) * (bj.w - bj.y);
            for (long long p = p0; p < p1; p++) {
                unsigned long long ki = skey[i];
                float4 bi = sbox[i];
                float  ai = (bi.z - bi.x) * (bi.w - bi.y);
                float lx = fmaxf(bi.x, bj.x);
                float ly = fmaxf(bi.y, bj.y);
                float rx = fminf(bi.z, bj.z);
                float ry = fminf(bi.w, bj.w);
                float iw = fmaxf(rx - lx, 0.0f);
                float ih = fmaxf(ry - ly, 0.0f);
                float inter = iw * ih;
                float iou = inter / (ai + aj - inter + 1e-12f);
                if (iou > NMS_T) {
                    int loser  = (kj > ki) ? i : j;
                    int winner = (kj > ki) ? j : i;
                    cluster_or32(&smask32[loser * NW32 + (winner >> 5)],
                                 1u << (winner & 31));
                }
                if (++i == j) {
                    i = 0; j++;
                    kj = skey[j]; bj = sbox[j];
                    aj = (bj.z - bj.x) * (bj.w - bj.y);
                }
            }
        }
    }

    // cluster sync #2: all sidx stores + mask bits landed in rank 0
    asm volatile("barrier.cluster.arrive.aligned;" ::: "memory");
    asm volatile("barrier.cluster.wait.aligned;"   ::: "memory");
    if (crank != 0) return;

    // ---- warp greedy scan: register rows + 2-way speculative accepts ----
    if (tid < 32) {
        const int lane = tid;
        unsigned long long a0 = 0, a1 = 0, a2 = 0, a3 = 0, a4 = 0, a5 = 0;
        int na = 0;
        for (int chunk = 0; chunk * 32 < M && na < NDET; chunk++) {
            int r = chunk * 32 + lane;
            bool haveR = (r < M);
            int i = haveR ? sidx[r] : 0;
            unsigned sc = haveR ? (unsigned)(skey[i] >> 32) : 0u;
            bool alive = (sc != 0u);
            unsigned long long r0 = 0, r1 = 0, r2 = 0, r3 = 0, r4 = 0, r5 = 0;
            if (haveR) {
                const unsigned long long* row = &smask64[i * NW64];
                r0 = row[0]; r1 = row[1]; r2 = row[2];
                r3 = row[3]; r4 = row[4]; r5 = row[5];
            }
            unsigned long long sup = (r0 & a0) | (r1 & a1) | (r2 & a2)
                                   | (r3 & a3) | (r4 & a4) | (r5 & a5);
            unsigned pend   = __ballot_sync(FULLM, alive && (sup == 0ull));
            unsigned aliveb = __ballot_sync(FULLM, alive);
            while (pend && na < NDET) {
                int l1 = __ffs(pend) - 1;
                unsigned rem = pend & (pend - 1);
                int l2 = rem ? (__ffs(rem) - 1) : -1;
                int i1 = __shfl_sync(FULLM, i, l1);
                int i2 = __shfl_sync(FULLM, i, (l2 >= 0) ? l2 : l1);
                // own-row suppression bits for i1 / i2 (register selects)
                int w1 = i1 >> 6;
                unsigned long long sel1 = (w1 == 0) ? r0 : (w1 == 1) ? r1
                                        : (w1 == 2) ? r2 : (w1 == 3) ? r3
                                        : (w1 == 4) ? r4 : r5;
                bool b1 = (sel1 >> (i1 & 63)) & 1ull;
                int w2 = i2 >> 6;
                unsigned long long sel2 = (w2 == 0) ? r0 : (w2 == 1) ? r1
                                        : (w2 == 2) ? r2 : (w2 == 3) ? r3
                                        : (w2 == 4) ? r4 : r5;
                bool b2 = (sel2 >> (i2 & 63)) & 1ull;
                unsigned s1 = __ballot_sync(FULLM, b1);
                unsigned s2 = __ballot_sync(FULLM, b2);
                // accept l1
                if (lane == l1) { aidx[na] = i; ascr[na] = sc; }
                na++;
                {
                    unsigned long long b = 1ull << (i1 & 63);
                    a0 |= (w1 == 0) ? b : 0ull; a1 |= (w1 == 1) ? b : 0ull;
                    a2 |= (w1 == 2) ? b : 0ull; a3 |= (w1 == 3) ? b : 0ull;
                    a4 |= (w1 == 4) ? b : 0ull; a5 |= (w1 == 5) ? b : 0ull;
                }
                pend = rem & ~s1;       // drop lanes suppressed by i1 (incl l2 if hit)
                bool ok2 = (l2 >= 0) && (na < NDET) && !((s1 >> l2) & 1u);
                if (ok2) {
                    if (lane == l2) { aidx[na] = i; ascr[na] = sc; }
                    na++;
                    unsigned long long b = 1ull << (i2 & 63);
                    a0 |= (w2 == 0) ? b : 0ull; a1 |= (w2 == 1) ? b : 0ull;
                    a2 |= (w2 == 2) ? b : 0ull; a3 |= (w2 == 3) ? b : 0ull;
                    a4 |= (w2 == 4) ? b : 0ull; a5 |= (w2 == 5) ? b : 0ull;
                    pend &= ~(1u << l2);
                    pend &= ~s2;        // drop lanes suppressed by i2
                }
            }
            if (na == NDET || aliveb != FULLM) break;  // done / later ranks dead
        }
        if (lane == 0) shNa = na;
    }
    __syncthreads();

    // ---- parallel output ----
    const int obase = c * NDET * 4;
    const int sbase = NFG * NDET * 4;        // 32000
    const int lbase = sbase + NFG * NDET;    // 40000
    const int vbase = lbase + NFG * NDET;    // 48000
    const float label = (float)(c + 1);
    const int na = shNa;

    for (int a = tid; a < na; a += T2) {
        float4 b = sbox[aidx[a]];
        out[obase + a * 4 + 0] = b.x;
        out[obase + a * 4 + 1] = b.y;
        out[obase + a * 4 + 2] = b.z;
        out[obase + a * 4 + 3] = b.w;
        int slot = c * NDET + a;
        out[sbase + slot] = __uint_as_float(ascr[a]);
        out[lbase + slot] = label;
        out[vbase + slot] = 1.0f;
    }
    const float4 b0 = shB0;
    for (int jt = na + tid; jt < NDET; jt += T2) {
        out[obase + jt * 4 + 0] = b0.x;
        out[obase + jt * 4 + 1] = b0.y;
        out[obase + jt * 4 + 2] = b0.z;
        out[obase + jt * 4 + 3] = b0.w;
        int slot = c * NDET + jt;
        out[sbase + slot] = 0.0f;
        out[lbase + slot] = label;
        out[vbase + slot] = 0.0f;
    }
}

extern "C" void kernel_launch(void* const* d_in, const int* in_sizes, int n_in,
                              void* d_out, int out_size) {
    const float* proposal = (const float*)d_in[0];
    const float* logits   = (const float*)d_in[1];
    const float* regs     = (const float*)d_in[2];
    const int*   imh      = (n_in >= 5) ? (const int*)d_in[3] : nullptr;
    const int*   imw      = (n_in >= 5) ? (const int*)d_in[4] : nullptr;
    float* outf = (float*)d_out;

    softmax_kernel<<<NPROP / SM_PROPS, 256>>>(logits);

    // PDL launch: nms ramps up while softmax still runs.
    cudaLaunchConfig_t cfg = {};
    cfg.gridDim  = dim3(NFG * CLU, 1, 1);
    cfg.blockDim = dim3(T2, 1, 1);
    cudaLaunchAttribute attrs[1];
    attrs[0].id = cudaLaunchAttributeProgrammaticStreamSerialization;
    attrs[0].val.programmaticStreamSerializationAllowed = 1;
    cfg.attrs = attrs;
    cfg.numAttrs = 1;
    cudaError_t err = cudaLaunchKernelEx(&cfg, nms_fused,
                                         proposal, regs, imh, imw, outf);
    if (err != cudaSuccess) {
        nms_fused<<<NFG * CLU, T2>>>(proposal, regs, imh, imw, outf);
    }
}